// round 13
// baseline (speedup 1.0000x reference)
#include <cuda_runtime.h>
#include <cuda_fp16.h>
#include <cstdint>
#include <math.h>

// ============================================================================
// sLSTM cell: gates = [x|h] @ [Wx|Wh]^T + b, exp-gate epilogue.
// R13: persistent CTAs (grid=304, dynamic tile grab via atomic counter) with a
//      CONTINUOUS 3-slot cp.async pipeline across tiles: next tile's pair0/1
//      issued before/through the epilogue; epilogue processed in 4 quarters
//      (each fits one 32KB slot) double-buffered in the two free slots.
//      GEMM math identical to R12 (fp16 single-pass, mma.sync.m16n8k16).
// ============================================================================

#define BATCH 16384
#define HDIM  1024
#define NTILES 4096
#define APLANE 8192
#define SLOT_BYTES 32768                 // one pair: 2 ktile-stages x 16KB
#define HDR_OFF (3 * SLOT_BYTES)         // 98304
#define SMEM_TOTAL (HDR_OFF + 128)       // 98432 -> 2 CTAs/SM
#define XQ_PRE 16896                     // pre region offset inside a quarter buf

__device__ int g_ctr;
__device__ __align__(16) __half g_Apack[(size_t)8192 * 4096]; // 67 MB
__device__ __align__(16) __half g_Wpack[(size_t)2048 * 4096]; // 17 MB

__device__ __forceinline__ uint32_t smem_u32(const void* p) {
    uint32_t a;
    asm("{ .reg .u64 t; cvta.to.shared.u64 t, %1; cvt.u32.u64 %0, t; }" : "=r"(a) : "l"(p));
    return a;
}

#define LDSM_X4(r, addr)                                                        \
    asm volatile("ldmatrix.sync.aligned.m8n8.x4.shared.b16 {%0,%1,%2,%3}, [%4];" \
                 : "=r"((r)[0]), "=r"((r)[1]), "=r"((r)[2]), "=r"((r)[3])       \
                 : "r"(addr))

#define MMA16816(d, a, b)                                                       \
    asm volatile("mma.sync.aligned.m16n8k16.row.col.f32.f16.f16.f32 "           \
                 "{%0,%1,%2,%3}, {%4,%5,%6,%7}, {%8,%9}, {%0,%1,%2,%3};"        \
                 : "+f"((d)[0]), "+f"((d)[1]), "+f"((d)[2]), "+f"((d)[3])       \
                 : "r"((a)[0]), "r"((a)[1]), "r"((a)[2]), "r"((a)[3]),          \
                   "r"((b)[0]), "r"((b)[1]))

#define CP_ASYNC16(dst, src) \
    asm volatile("cp.async.cg.shared.global [%0], [%1], 16;" :: "r"(dst), "l"(src))
#define CP_COMMIT() asm volatile("cp.async.commit_group;" ::: "memory")
#define CP_WAIT0()  asm volatile("cp.async.wait_group 0;" ::: "memory")
#define CP_WAIT1()  asm volatile("cp.async.wait_group 1;" ::: "memory")

__device__ __forceinline__ uint32_t swz(int row, int ch) {
    return (uint32_t)(row * 64 + ((ch ^ ((row >> 1) & 3)) << 4));
}

// ============================== pack kernel =================================
__global__ __launch_bounds__(128) void pack_kernel(
    const float* __restrict__ x, const float* __restrict__ h,
    const float* __restrict__ Wx, const float* __restrict__ Wh)
{
    if (blockIdx.x == 0 && threadIdx.x == 0) g_ctr = 0;   // reset tile counter
    const int bt = blockIdx.x, t = threadIdx.x;
    const bool isA = bt < 8192;
    const int tile = isA ? bt : bt - 8192;
    const int kt = tile & 63;
    const int rt = tile >> 6;
    const float* src = (kt < 32) ? (isA ? x : Wx) : (isA ? h : Wh);
    const int kbase = (kt & 31) * 32;
    __half* dst = (isA ? g_Apack : g_Wpack) + (size_t)tile * 4096;

    #pragma unroll
    for (int i = 0; i < 8; i++) {
        const int cc = i * 128 + t;
        const int r = cc >> 3, k4 = cc & 7;
        const int grow = isA ? (rt * 128 + r)
                             : ((r >> 5) * HDIM + rt * 32 + (r & 31));
        float4 v = *(const float4*)(src + (size_t)grow * 1024 + kbase + k4 * 4);
        __half2 p0 = __floats2half2_rn(v.x, v.y);
        __half2 p1 = __floats2half2_rn(v.z, v.w);
        *(uint2*)(dst + r * 32 + k4 * 4) =
            make_uint2(*(uint32_t*)&p0, *(uint32_t*)&p1);
    }
}

// =============================== main kernel ================================
__global__ __launch_bounds__(256, 2) void slstm_main(
    const float* __restrict__ c_in, const float* __restrict__ n_in,
    const float* __restrict__ m_in, const float* __restrict__ bias,
    float* __restrict__ out)
{
    extern __shared__ char smraw[];
    const uint32_t sb = smem_u32(smraw);
    const int t = threadIdx.x, lane = t & 31, wid = t >> 5;
    const int wm = wid >> 1, wn = wid & 1;
    int* hdr = (int*)(smraw + HDR_OFF);

    if (t == 0) hdr[0] = atomicAdd(&g_ctr, 1);
    __syncthreads();
    int cur = hdr[0];
    if (cur >= NTILES) return;

    // per-thread LDSM offsets
    uint32_t aoff[2], woff[4];
    #pragma unroll
    for (int tm = 0; tm < 2; tm++) {
        const int r = wm * 32 + tm * 16 + (lane & 15);
        aoff[tm] = swz(r, lane >> 4);
    }
    #pragma unroll
    for (int p = 0; p < 4; p++) {
        const int r = wn * 64 + p * 16 + ((lane >> 4) << 3) + (lane & 7);
        woff[p] = swz(r, (lane >> 3) & 1);
    }
    const int jj4 = (t & 7) * 4;

    auto tileA = [&](int tile) -> const char* {
        return (const char*)g_Apack + (size_t)((tile >> 5) * 64) * 8192;
    };
    auto tileW = [&](int tile) -> const char* {
        return (const char*)g_Wpack + (size_t)((tile & 31) * 64) * 8192;
    };

    // load one PAIR (ktiles kt0, kt0+1) into a slot; one commit group
    auto load_pair = [&](uint32_t slotaddr, const char* Ab, const char* Wb, int kt0) {
        #pragma unroll
        for (int s2 = 0; s2 < 2; s2++) {
            const int kt = kt0 + s2;
            const uint32_t d0 = slotaddr + s2 * 16384;
            #pragma unroll
            for (int i = 0; i < 4; i++) {
                const int c = i * 256 + t;
                const int plane = c >> 9, w = c & 511;
                const int row = w >> 2, ch = w & 3;
                const char* src = (plane == 0)
                    ? Ab + (size_t)kt * 8192 + w * 16
                    : Wb + (size_t)kt * 8192 + w * 16;
                CP_ASYNC16(d0 + plane * APLANE + swz(row, ch), src);
            }
        }
        CP_COMMIT();
    };

    float acc[2][8][4];
    uint32_t afr[2][2][4], wfr[2][4][4];
    auto load_frags = [&](int buf, uint32_t st, int ks) {
        const uint32_t kx = ks ? 32u : 0u;
        #pragma unroll
        for (int tm = 0; tm < 2; tm++)
            LDSM_X4(afr[buf][tm], st + (aoff[tm] ^ kx));
        const uint32_t wst = st + APLANE;
        #pragma unroll
        for (int p = 0; p < 4; p++)
            LDSM_X4(wfr[buf][p], wst + (woff[p] ^ kx));
    };
    auto mma_frags = [&](int buf) {
        #pragma unroll
        for (int tm = 0; tm < 2; tm++)
            #pragma unroll
            for (int tn = 0; tn < 8; tn++)
                MMA16816(acc[tm][tn], afr[buf][tm],
                         (&wfr[buf][tn >> 1][(tn & 1) * 2]));
    };
    auto compute_pair = [&](uint32_t slotaddr) {
        const uint32_t stA = slotaddr, stB = slotaddr + 16384;
        load_frags(0, stA, 0);
        load_frags(1, stA, 1);  mma_frags(0);
        load_frags(0, stB, 0);  mma_frags(1);
        load_frags(1, stB, 1);  mma_frags(0);
        mma_frags(1);
    };

    const size_t BH = (size_t)BATCH * HDIM;
    int phase = 0;

    // prologue: tile cur, pairs 0 and 1
    load_pair(sb + 0 * SLOT_BYTES, tileA(cur), tileW(cur), 0);
    load_pair(sb + 1 * SLOT_BYTES, tileA(cur), tileW(cur), 2);

    while (true) {
        const int nt = cur & 31, mt = cur >> 5;
        const char* Ab = tileA(cur);
        const char* Wb = tileW(cur);

        #pragma unroll
        for (int a = 0; a < 2; a++)
            #pragma unroll
            for (int b = 0; b < 8; b++)
                #pragma unroll
                for (int e = 0; e < 4; e++) acc[a][b][e] = 0.0f;

        float4 b4[4];
        #pragma unroll
        for (int g = 0; g < 4; g++)
            b4[g] = *(const float4*)(bias + g * HDIM + nt * 32 + jj4);

        int nxt = NTILES;
        for (int p = 0; p < 32; p++) {
            if (p == 31 && nxt >= NTILES) { CP_WAIT0(); } else { CP_WAIT1(); }
            __syncthreads();
            if (p == 29 && t == 0) hdr[1] = atomicAdd(&g_ctr, 1);
            if (p <= 29) {
                load_pair(sb + ((phase + p + 2) % 3) * SLOT_BYTES, Ab, Wb, 2 * (p + 2));
            } else if (p == 30) {
                nxt = hdr[1];
                if (nxt < NTILES)
                    load_pair(sb + ((phase + 2) % 3) * SLOT_BYTES,
                              tileA(nxt), tileW(nxt), 0);
            }
            compute_pair(sb + ((phase + p) % 3) * SLOT_BYTES);
        }

        // =========================== epilogue ===============================
        const uint32_t F1 = sb + (phase % 3) * SLOT_BYTES;
        const uint32_t F2 = sb + ((phase + 1) % 3) * SLOT_BYTES;
        const bool has_nxt = (nxt < NTILES);

        auto preQ = [&](int q, uint32_t buf) {
            const float* srcs[3] = {c_in, n_in, m_in};
            const int row = t >> 3, c16 = t & 7;
            #pragma unroll
            for (int i = 0; i < 3; i++) {
                const char* src = (const char*)srcs[i]
                    + ((size_t)(mt * 128 + q * 32 + row) * HDIM + nt * 32) * 4
                    + c16 * 16;
                CP_ASYNC16(buf + XQ_PRE + i * 4096 + row * 128 + c16 * 16, src);
            }
            CP_COMMIT();
        };
        auto xchgQ = [&](int q, uint32_t buf) {
            if (wm != q) return;
            float* xf = (float*)(smraw + (buf - sb));
            #pragma unroll
            for (int tm = 0; tm < 2; tm++)
                #pragma unroll
                for (int tn = 0; tn < 8; tn++) {
                    const int row = tm * 16 + (lane >> 2);
                    const int col = wn * 64 + tn * 8 + (lane & 3) * 2;
                    xf[row * 132 + col]           = acc[tm][tn][0];
                    xf[row * 132 + col + 1]       = acc[tm][tn][1];
                    xf[(row + 8) * 132 + col]     = acc[tm][tn][2];
                    xf[(row + 8) * 132 + col + 1] = acc[tm][tn][3];
                }
        };
        auto computeQ = [&](int q, uint32_t buf) {
            float* xf = (float*)(smraw + (buf - sb));
            float* pf = (float*)(smraw + (buf - sb) + XQ_PRE);
            const int rl = t >> 3;
            float4 c4 = *(float4*)(pf + 0 * 1024 + rl * 32 + jj4);
            float4 n4 = *(float4*)(pf + 1 * 1024 + rl * 32 + jj4);
            float4 m4 = *(float4*)(pf + 2 * 1024 + rl * 32 + jj4);
            const float* gr = xf + rl * 132;
            float4 ho, co, no, mo4;
            #pragma unroll
            for (int e = 0; e < 4; e++) {
                const float iv = gr[0 * 32 + jj4 + e] + ((const float*)&b4[0])[e];
                const float fv = gr[1 * 32 + jj4 + e] + ((const float*)&b4[1])[e];
                const float zv = gr[2 * 32 + jj4 + e] + ((const float*)&b4[2])[e];
                const float ov = gr[3 * 32 + jj4 + e] + ((const float*)&b4[3])[e];
                const float cv = ((const float*)&c4)[e];
                const float nv = ((const float*)&n4)[e];
                const float mv = ((const float*)&m4)[e];
                const float mn = fmaxf(fv + mv, iv);
                const float fg = __expf(fv + mv - mn);
                const float ig = __expf(iv - mn);
                const float zg = tanhf(zv);
                const float og = 1.0f / (1.0f + __expf(-ov));
                const float cn = fg * cv + ig * zg;
                const float nn = fg * nv + ig;
                const float hn = og * (cn / fmaxf(fabsf(nn), 1.0f));
                ((float*)&ho)[e]  = hn;
                ((float*)&co)[e]  = cn;
                ((float*)&no)[e]  = nn;
                ((float*)&mo4)[e] = mn;
            }
            float* ob = out + (size_t)(mt * 128 + q * 32 + rl) * HDIM + nt * 32 + jj4;
            *(float4*)(ob)          = ho;
            *(float4*)(ob + BH)     = co;
            *(float4*)(ob + 2 * BH) = no;
            *(float4*)(ob + 3 * BH) = mo4;
        };

        __syncthreads();            // mainloop smem reads complete
        preQ(0, F1);
        preQ(1, F2);
        xchgQ(0, F1);
        CP_WAIT1();                 // preQ0 (and older) done
        __syncthreads();
        computeQ(0, F1);
        xchgQ(1, F2);
        CP_WAIT0();                 // preQ1 done
        __syncthreads();            // Q0 reads done -> F1 reusable
        preQ(2, F1);
        computeQ(1, F2);
        xchgQ(2, F1);
        CP_WAIT0();                 // preQ2 done
        __syncthreads();            // Q1 reads done -> F2 reusable
        preQ(3, F2);
        computeQ(2, F1);
        xchgQ(3, F2);
        CP_WAIT0();                 // preQ3 done
        __syncthreads();            // Q2 reads done -> F1 free for next pair1
        if (has_nxt)
            load_pair(F1, tileA(nxt), tileW(nxt), 2);   // next tile pair1
        computeQ(3, F2);

        if (!has_nxt) return;
        phase = (phase + 2) % 3;
        cur = nxt;
    }
}

// ================================ launch ====================================
extern "C" void kernel_launch(void* const* d_in, const int* in_sizes, int n_in,
                              void* d_out, int out_size) {
    const float* x    = (const float*)d_in[0];
    const float* h    = (const float*)d_in[1];
    const float* c    = (const float*)d_in[2];
    const float* n    = (const float*)d_in[3];
    const float* m    = (const float*)d_in[4];
    const float* Wx   = (const float*)d_in[5];
    const float* Wh   = (const float*)d_in[6];
    const float* bias = (const float*)d_in[7];
    float* out = (float*)d_out;

    pack_kernel<<<10240, 128>>>(x, h, Wx, Wh);

    cudaFuncSetAttribute(slstm_main, cudaFuncAttributeMaxDynamicSharedMemorySize,
                         SMEM_TOTAL);
    slstm_main<<<304, 256, SMEM_TOTAL>>>(c, n, m, bias, out);
}

// round 14
// speedup vs baseline: 1.0408x; 1.0408x over previous
#include <cuda_runtime.h>
#include <cuda_fp16.h>
#include <cstdint>
#include <math.h>

// ============================================================================
// sLSTM cell: gates = [x|h] @ [Wx|Wh]^T + b, exp-gate epilogue.
// R14: mainloop operand delivery moved OFF the LSU/crossbar: pack kernel
//      stores pre-swizzled planes; one thread issues cp.async.bulk (16KB x2)
//      per ktile-pair against an mbarrier (expect_tx). LDSM-side crossbar
//      demand drops 64KB -> 48KB per CTA-ktile. GEMM + epilogue = R12.
// ============================================================================

#define BATCH 16384
#define HDIM  1024
#define NKT   64
#define APLANE 8192
#define SLOT_BYTES 32768                 // A(kt0)|A(kt1)|W(kt0)|W(kt1)
#define HDR_OFF (3 * SLOT_BYTES)         // 98304: 3 mbarriers live here
#define SMEM_TOTAL (HDR_OFF + 128)       // 98432 -> 2 CTAs/SM

#define XCHG_BYTES (64 * 132 * 4)        // 33792: half-tile fp32 exchange
#define PRE_OFF    XCHG_BYTES            // c/n/m prefetch: 3 x 16KB

__device__ __align__(16) __half g_Apack[(size_t)8192 * 4096]; // 67 MB
__device__ __align__(16) __half g_Wpack[(size_t)2048 * 4096]; // 17 MB

__device__ __forceinline__ uint32_t smem_u32(const void* p) {
    uint32_t a;
    asm("{ .reg .u64 t; cvta.to.shared.u64 t, %1; cvt.u32.u64 %0, t; }" : "=r"(a) : "l"(p));
    return a;
}

#define LDSM_X4(r, addr)                                                        \
    asm volatile("ldmatrix.sync.aligned.m8n8.x4.shared.b16 {%0,%1,%2,%3}, [%4];" \
                 : "=r"((r)[0]), "=r"((r)[1]), "=r"((r)[2]), "=r"((r)[3])       \
                 : "r"(addr))

#define MMA16816(d, a, b)                                                       \
    asm volatile("mma.sync.aligned.m16n8k16.row.col.f32.f16.f16.f32 "           \
                 "{%0,%1,%2,%3}, {%4,%5,%6,%7}, {%8,%9}, {%0,%1,%2,%3};"        \
                 : "+f"((d)[0]), "+f"((d)[1]), "+f"((d)[2]), "+f"((d)[3])       \
                 : "r"((a)[0]), "r"((a)[1]), "r"((a)[2]), "r"((a)[3]),          \
                   "r"((b)[0]), "r"((b)[1]))

#define CP_ASYNC16(dst, src) \
    asm volatile("cp.async.cg.shared.global [%0], [%1], 16;" :: "r"(dst), "l"(src))
#define CP_COMMIT() asm volatile("cp.async.commit_group;" ::: "memory")
#define CP_WAIT0()  asm volatile("cp.async.wait_group 0;" ::: "memory")
#define CP_WAIT1()  asm volatile("cp.async.wait_group 1;" ::: "memory")

#define MBARRIER_INIT(addr, cnt) \
    asm volatile("mbarrier.init.shared.b64 [%0], %1;" :: "r"(addr), "r"(cnt) : "memory")
#define MBARRIER_EXPECT_TX(addr, bytes) \
    asm volatile("mbarrier.arrive.expect_tx.shared.b64 _, [%0], %1;" :: "r"(addr), "r"(bytes) : "memory")
#define BULK_G2S(dst, src, bytes, mbar)                                                      \
    asm volatile("cp.async.bulk.shared::cta.global.mbarrier::complete_tx::bytes "            \
                 "[%0], [%1], %2, [%3];"                                                     \
                 :: "r"(dst), "l"(src), "r"(bytes), "r"(mbar) : "memory")

#define MBARRIER_WAIT_PARITY(mbar, parity) do {                                   \
    uint32_t _m = (mbar); uint32_t _p = (parity); uint32_t _d;                    \
    asm volatile("{\n\t.reg .pred p;\n\t"                                         \
        "mbarrier.try_wait.parity.acquire.cta.shared::cta.b64 p, [%1], %2;\n\t"   \
        "selp.b32 %0, 1, 0, p;\n\t}"                                              \
        : "=r"(_d) : "r"(_m), "r"(_p) : "memory");                                \
    if (!_d) {                                                                    \
        asm volatile("{\n\t.reg .pred P1;\n\t"                                    \
            "WL_%=:\n\t"                                                          \
            "mbarrier.try_wait.parity.acquire.cta.shared::cta.b64 P1, [%0], %1, 0x989680;\n\t" \
            "@P1 bra.uni WD_%=;\n\t"                                              \
            "bra.uni WL_%=;\n\t"                                                  \
            "WD_%=:\n\t}"                                                         \
            :: "r"(_m), "r"(_p) : "memory");                                      \
    }                                                                             \
} while (0)

__device__ __forceinline__ uint32_t swz(int row, int ch) {
    return (uint32_t)(row * 64 + ((ch ^ ((row >> 1) & 3)) << 4));
}

// ============================== pack kernel =================================
// Writes planes PRE-SWIZZLED so the main kernel can bulk-copy them linearly.
__global__ __launch_bounds__(128) void pack_kernel(
    const float* __restrict__ x, const float* __restrict__ h,
    const float* __restrict__ Wx, const float* __restrict__ Wh)
{
    const int bt = blockIdx.x, t = threadIdx.x;
    const bool isA = bt < 8192;
    const int tile = isA ? bt : bt - 8192;
    const int kt = tile & 63;
    const int rt = tile >> 6;
    const float* src = (kt < 32) ? (isA ? x : Wx) : (isA ? h : Wh);
    const int kbase = (kt & 31) * 32;
    __half* dst = (isA ? g_Apack : g_Wpack) + (size_t)tile * 4096;

    #pragma unroll
    for (int i = 0; i < 8; i++) {
        const int cc = i * 128 + t;
        const int r = cc >> 3, k4 = cc & 7;
        const int grow = isA ? (rt * 128 + r)
                             : ((r >> 5) * HDIM + rt * 32 + (r & 31));
        float4 v = *(const float4*)(src + (size_t)grow * 1024 + kbase + k4 * 4);
        __half2 p0 = __floats2half2_rn(v.x, v.y);
        __half2 p1 = __floats2half2_rn(v.z, v.w);
        // swizzled element offset (halves): 16B-chunk ch=k4>>1 XORed by (r>>1)&3
        const int eoff = r * 32 + (((k4 >> 1) ^ ((r >> 1) & 3)) << 3) + (k4 & 1) * 4;
        *(uint2*)(dst + eoff) = make_uint2(*(uint32_t*)&p0, *(uint32_t*)&p1);
    }
}

// =============================== main kernel ================================
__global__ __launch_bounds__(256, 2) void slstm_main(
    const float* __restrict__ c_in, const float* __restrict__ n_in,
    const float* __restrict__ m_in, const float* __restrict__ bias,
    float* __restrict__ out)
{
    extern __shared__ char smraw[];
    const uint32_t sb = smem_u32(smraw);
    const int t = threadIdx.x, lane = t & 31, wid = t >> 5;
    const int nt = blockIdx.x, mt = blockIdx.y;
    const int wm = wid >> 1, wn = wid & 1;
    const uint32_t MB = sb + HDR_OFF;      // 3 mbarriers, 8B apart

    const char* Abase = (const char*)g_Apack + (size_t)(mt * 64) * 8192;
    const char* Wbase = (const char*)g_Wpack + (size_t)(nt * 64) * 8192;

    uint32_t aoff[2], woff[4];
    #pragma unroll
    for (int tm = 0; tm < 2; tm++) {
        const int r = wm * 32 + tm * 16 + (lane & 15);
        aoff[tm] = swz(r, lane >> 4);
    }
    #pragma unroll
    for (int p = 0; p < 4; p++) {
        const int r = wn * 64 + p * 16 + ((lane >> 4) << 3) + (lane & 7);
        woff[p] = swz(r, (lane >> 3) & 1);
    }

    if (t == 0) {
        #pragma unroll
        for (int s = 0; s < 3; s++) MBARRIER_INIT(MB + s * 8, 1);
    }
    __syncthreads();

    // issue one pair (ktiles 2p, 2p+1): 2 x 16KB bulk copies, one barrier
    auto issue_pair = [&](int p) {
        const int s = p % 3;
        const uint32_t slot = sb + s * SLOT_BYTES;
        MBARRIER_EXPECT_TX(MB + s * 8, 32768u);
        BULK_G2S(slot,         Abase + (size_t)(2 * p) * 8192, 16384u, MB + s * 8);
        BULK_G2S(slot + 16384, Wbase + (size_t)(2 * p) * 8192, 16384u, MB + s * 8);
    };

    float acc[2][8][4];
    #pragma unroll
    for (int a = 0; a < 2; a++)
        #pragma unroll
        for (int b = 0; b < 8; b++)
            #pragma unroll
            for (int e = 0; e < 4; e++) acc[a][b][e] = 0.0f;

    uint32_t afr[2][2][4], wfr[2][4][4];
    auto load_frags = [&](int buf, uint32_t aa, uint32_t wa, int ks) {
        const uint32_t kx = ks ? 32u : 0u;
        #pragma unroll
        for (int tm = 0; tm < 2; tm++)
            LDSM_X4(afr[buf][tm], aa + (aoff[tm] ^ kx));
        #pragma unroll
        for (int p = 0; p < 4; p++)
            LDSM_X4(wfr[buf][p], wa + (woff[p] ^ kx));
    };
    auto mma_frags = [&](int buf) {
        #pragma unroll
        for (int tm = 0; tm < 2; tm++)
            #pragma unroll
            for (int tn = 0; tn < 8; tn++)
                MMA16816(acc[tm][tn], afr[buf][tm],
                         (&wfr[buf][tn >> 1][(tn & 1) * 2]));
    };
    auto compute_pair = [&](uint32_t slot) {
        const uint32_t a0 = slot, a1 = slot + 8192;
        const uint32_t w0 = slot + 16384, w1 = slot + 24576;
        load_frags(0, a0, w0, 0);
        load_frags(1, a0, w0, 1);  mma_frags(0);
        load_frags(0, a1, w1, 0);  mma_frags(1);
        load_frags(1, a1, w1, 1);  mma_frags(0);
        mma_frags(1);
    };

    // prologue: pairs 0,1
    if (t == 0) { issue_pair(0); issue_pair(1); }

    // main loop: 32 pairs; slot s = p%3, parity = (p/3)&1
    for (int p = 0; p < 32; p++) {
        MBARRIER_WAIT_PARITY(MB + (p % 3) * 8, (p / 3) & 1);
        __syncthreads();                 // pair p-1 consumed by all warps
        if (p <= 29 && t == 0) issue_pair(p + 2);
        compute_pair(sb + (p % 3) * SLOT_BYTES);
    }

    // ===================== epilogue (R12 scheme) ============================
    __syncthreads();   // all mainloop smem reads complete

    {
        const float* srcs[3] = {c_in, n_in, m_in};
        #pragma unroll
        for (int i = 0; i < 12; i++) {
            const int c = i * 256 + t;
            const int p = c >> 10, w = c & 1023;
            const int row = w >> 3, col16 = w & 7;
            const char* src = (const char*)srcs[p]
                + ((size_t)(mt * 128 + row) * HDIM + nt * 32) * 4 + col16 * 16;
            CP_ASYNC16(sb + PRE_OFF + p * 16384 + w * 16, src);
        }
        CP_COMMIT();
    }

    const int jc4 = t & 7;
    const int rp  = t >> 3;
    const int jj4 = jc4 * 4;
    float4 b4[4];
    #pragma unroll
    for (int g = 0; g < 4; g++)
        b4[g] = *(const float4*)(bias + g * HDIM + nt * 32 + jj4);

    float* smf = (float*)smraw;
    float* pre = (float*)(smraw + PRE_OFF);
    const size_t BH = (size_t)BATCH * HDIM;

    #pragma unroll
    for (int H = 0; H < 2; H++) {
        if (wm >> 1 == H) {
            #pragma unroll
            for (int tm = 0; tm < 2; tm++)
                #pragma unroll
                for (int tn = 0; tn < 8; tn++) {
                    const int row = (wm & 1) * 32 + tm * 16 + (lane >> 2);
                    const int col = wn * 64 + tn * 8 + (lane & 3) * 2;
                    smf[row * 132 + col]           = acc[tm][tn][0];
                    smf[row * 132 + col + 1]       = acc[tm][tn][1];
                    smf[(row + 8) * 132 + col]     = acc[tm][tn][2];
                    smf[(row + 8) * 132 + col + 1] = acc[tm][tn][3];
                }
        }
        if (H == 0) CP_WAIT0();
        __syncthreads();

        #pragma unroll
        for (int r2 = 0; r2 < 2; r2++) {
            const int rloc = rp * 2 + r2;
            const int grow = mt * 128 + H * 64 + rloc;
            const int prow = H * 64 + rloc;
            float4 c4 = *(float4*)(pre + 0 * 4096 + prow * 32 + jj4);
            float4 n4 = *(float4*)(pre + 1 * 4096 + prow * 32 + jj4);
            float4 m4 = *(float4*)(pre + 2 * 4096 + prow * 32 + jj4);
            float4 ho, co, no, mo4;
            const float* gr = smf + rloc * 132;
            #pragma unroll
            for (int e = 0; e < 4; e++) {
                const float iv = gr[0 * 32 + jj4 + e] + ((const float*)&b4[0])[e];
                const float fv = gr[1 * 32 + jj4 + e] + ((const float*)&b4[1])[e];
                const float zv = gr[2 * 32 + jj4 + e] + ((const float*)&b4[2])[e];
                const float ov = gr[3 * 32 + jj4 + e] + ((const float*)&b4[3])[e];
                const float cv = ((const float*)&c4)[e];
                const float nv = ((const float*)&n4)[e];
                const float mv = ((const float*)&m4)[e];
                const float mn = fmaxf(fv + mv, iv);
                const float fg = __expf(fv + mv - mn);
                const float ig = __expf(iv - mn);
                const float zg = tanhf(zv);
                const float og = 1.0f / (1.0f + __expf(-ov));
                const float cn = fg * cv + ig * zg;
                const float nn = fg * nv + ig;
                const float hn = og * (cn / fmaxf(fabsf(nn), 1.0f));
                ((float*)&ho)[e]  = hn;
                ((float*)&co)[e]  = cn;
                ((float*)&no)[e]  = nn;
                ((float*)&mo4)[e] = mn;
            }
            float* ob = out + (size_t)grow * HDIM + nt * 32 + jj4;
            *(float4*)(ob)           = ho;
            *(float4*)(ob + BH)      = co;
            *(float4*)(ob + 2 * BH)  = no;
            *(float4*)(ob + 3 * BH)  = mo4;
        }
        if (H == 0) __syncthreads();
    }
}

// ================================ launch ====================================
extern "C" void kernel_launch(void* const* d_in, const int* in_sizes, int n_in,
                              void* d_out, int out_size) {
    const float* x    = (const float*)d_in[0];
    const float* h    = (const float*)d_in[1];
    const float* c    = (const float*)d_in[2];
    const float* n    = (const float*)d_in[3];
    const float* m    = (const float*)d_in[4];
    const float* Wx   = (const float*)d_in[5];
    const float* Wh   = (const float*)d_in[6];
    const float* bias = (const float*)d_in[7];
    float* out = (float*)d_out;

    pack_kernel<<<10240, 128>>>(x, h, Wx, Wh);

    cudaFuncSetAttribute(slstm_main, cudaFuncAttributeMaxDynamicSharedMemorySize,
                         SMEM_TOTAL);
    dim3 grid(32, 128);   // (nt, mt)
    slstm_main<<<grid, 256, SMEM_TOTAL>>>(c, n, m, bias, out);
}

// round 15
// speedup vs baseline: 1.0540x; 1.0126x over previous
#include <cuda_runtime.h>
#include <cuda_fp16.h>
#include <cstdint>
#include <math.h>

// ============================================================================
// sLSTM cell: gates = [x|h] @ [Wx|Wh]^T + b, exp-gate epilogue.
// R15 = R14 (bulk-copy mainloop feeds, 3-slot mbarrier pipeline, overlapped
//      epilogue) + two changes:
//      (1) mainloop order sync -> issue(p+2) -> wait(p): producer not blocked
//          behind consumer wait.
//      (2) epilogue transcendentals forced to MUFU approx forms regardless of
//          compile flags: tanh.approx, sigmoid via tanh, rcp.approx division.
// ============================================================================

#define BATCH 16384
#define HDIM  1024
#define NKT   64
#define APLANE 8192
#define SLOT_BYTES 32768                 // A(kt0)|A(kt1)|W(kt0)|W(kt1)
#define HDR_OFF (3 * SLOT_BYTES)         // 98304: 3 mbarriers live here
#define SMEM_TOTAL (HDR_OFF + 128)       // 98432 -> 2 CTAs/SM

#define XCHG_BYTES (64 * 132 * 4)        // 33792: half-tile fp32 exchange
#define PRE_OFF    XCHG_BYTES            // c/n/m prefetch: 3 x 16KB

__device__ __align__(16) __half g_Apack[(size_t)8192 * 4096]; // 67 MB
__device__ __align__(16) __half g_Wpack[(size_t)2048 * 4096]; // 17 MB

__device__ __forceinline__ uint32_t smem_u32(const void* p) {
    uint32_t a;
    asm("{ .reg .u64 t; cvta.to.shared.u64 t, %1; cvt.u32.u64 %0, t; }" : "=r"(a) : "l"(p));
    return a;
}
__device__ __forceinline__ float tanh_approx(float x) {
    float y;
    asm("tanh.approx.f32 %0, %1;" : "=f"(y) : "f"(x));
    return y;
}
__device__ __forceinline__ float rcp_approx(float x) {
    float y;
    asm("rcp.approx.f32 %0, %1;" : "=f"(y) : "f"(x));
    return y;
}
__device__ __forceinline__ float exp_approx(float x) {
    float y;
    asm("ex2.approx.f32 %0, %1;" : "=f"(y) : "f"(x * 1.442695041f));
    return y;
}

#define LDSM_X4(r, addr)                                                        \
    asm volatile("ldmatrix.sync.aligned.m8n8.x4.shared.b16 {%0,%1,%2,%3}, [%4];" \
                 : "=r"((r)[0]), "=r"((r)[1]), "=r"((r)[2]), "=r"((r)[3])       \
                 : "r"(addr))

#define MMA16816(d, a, b)                                                       \
    asm volatile("mma.sync.aligned.m16n8k16.row.col.f32.f16.f16.f32 "           \
                 "{%0,%1,%2,%3}, {%4,%5,%6,%7}, {%8,%9}, {%0,%1,%2,%3};"        \
                 : "+f"((d)[0]), "+f"((d)[1]), "+f"((d)[2]), "+f"((d)[3])       \
                 : "r"((a)[0]), "r"((a)[1]), "r"((a)[2]), "r"((a)[3]),          \
                   "r"((b)[0]), "r"((b)[1]))

#define CP_ASYNC16(dst, src) \
    asm volatile("cp.async.cg.shared.global [%0], [%1], 16;" :: "r"(dst), "l"(src))
#define CP_COMMIT() asm volatile("cp.async.commit_group;" ::: "memory")
#define CP_WAIT0()  asm volatile("cp.async.wait_group 0;" ::: "memory")

#define MBARRIER_INIT(addr, cnt) \
    asm volatile("mbarrier.init.shared.b64 [%0], %1;" :: "r"(addr), "r"(cnt) : "memory")
#define MBARRIER_EXPECT_TX(addr, bytes) \
    asm volatile("mbarrier.arrive.expect_tx.shared.b64 _, [%0], %1;" :: "r"(addr), "r"(bytes) : "memory")
#define BULK_G2S(dst, src, bytes, mbar)                                                      \
    asm volatile("cp.async.bulk.shared::cta.global.mbarrier::complete_tx::bytes "            \
                 "[%0], [%1], %2, [%3];"                                                     \
                 :: "r"(dst), "l"(src), "r"(bytes), "r"(mbar) : "memory")

#define MBARRIER_WAIT_PARITY(mbar, parity) do {                                   \
    uint32_t _m = (mbar); uint32_t _p = (parity); uint32_t _d;                    \
    asm volatile("{\n\t.reg .pred p;\n\t"                                         \
        "mbarrier.try_wait.parity.acquire.cta.shared::cta.b64 p, [%1], %2;\n\t"   \
        "selp.b32 %0, 1, 0, p;\n\t}"                                              \
        : "=r"(_d) : "r"(_m), "r"(_p) : "memory");                                \
    if (!_d) {                                                                    \
        asm volatile("{\n\t.reg .pred P1;\n\t"                                    \
            "WL_%=:\n\t"                                                          \
            "mbarrier.try_wait.parity.acquire.cta.shared::cta.b64 P1, [%0], %1, 0x989680;\n\t" \
            "@P1 bra.uni WD_%=;\n\t"                                              \
            "bra.uni WL_%=;\n\t"                                                  \
            "WD_%=:\n\t}"                                                         \
            :: "r"(_m), "r"(_p) : "memory");                                      \
    }                                                                             \
} while (0)

__device__ __forceinline__ uint32_t swz(int row, int ch) {
    return (uint32_t)(row * 64 + ((ch ^ ((row >> 1) & 3)) << 4));
}

// ============================== pack kernel =================================
// Writes planes PRE-SWIZZLED so the main kernel can bulk-copy them linearly.
__global__ __launch_bounds__(128) void pack_kernel(
    const float* __restrict__ x, const float* __restrict__ h,
    const float* __restrict__ Wx, const float* __restrict__ Wh)
{
    const int bt = blockIdx.x, t = threadIdx.x;
    const bool isA = bt < 8192;
    const int tile = isA ? bt : bt - 8192;
    const int kt = tile & 63;
    const int rt = tile >> 6;
    const float* src = (kt < 32) ? (isA ? x : Wx) : (isA ? h : Wh);
    const int kbase = (kt & 31) * 32;
    __half* dst = (isA ? g_Apack : g_Wpack) + (size_t)tile * 4096;

    #pragma unroll
    for (int i = 0; i < 8; i++) {
        const int cc = i * 128 + t;
        const int r = cc >> 3, k4 = cc & 7;
        const int grow = isA ? (rt * 128 + r)
                             : ((r >> 5) * HDIM + rt * 32 + (r & 31));
        float4 v = *(const float4*)(src + (size_t)grow * 1024 + kbase + k4 * 4);
        __half2 p0 = __floats2half2_rn(v.x, v.y);
        __half2 p1 = __floats2half2_rn(v.z, v.w);
        const int eoff = r * 32 + (((k4 >> 1) ^ ((r >> 1) & 3)) << 3) + (k4 & 1) * 4;
        *(uint2*)(dst + eoff) = make_uint2(*(uint32_t*)&p0, *(uint32_t*)&p1);
    }
}

// =============================== main kernel ================================
__global__ __launch_bounds__(256, 2) void slstm_main(
    const float* __restrict__ c_in, const float* __restrict__ n_in,
    const float* __restrict__ m_in, const float* __restrict__ bias,
    float* __restrict__ out)
{
    extern __shared__ char smraw[];
    const uint32_t sb = smem_u32(smraw);
    const int t = threadIdx.x, lane = t & 31, wid = t >> 5;
    const int nt = blockIdx.x, mt = blockIdx.y;
    const int wm = wid >> 1, wn = wid & 1;
    const uint32_t MB = sb + HDR_OFF;

    const char* Abase = (const char*)g_Apack + (size_t)(mt * 64) * 8192;
    const char* Wbase = (const char*)g_Wpack + (size_t)(nt * 64) * 8192;

    uint32_t aoff[2], woff[4];
    #pragma unroll
    for (int tm = 0; tm < 2; tm++) {
        const int r = wm * 32 + tm * 16 + (lane & 15);
        aoff[tm] = swz(r, lane >> 4);
    }
    #pragma unroll
    for (int p = 0; p < 4; p++) {
        const int r = wn * 64 + p * 16 + ((lane >> 4) << 3) + (lane & 7);
        woff[p] = swz(r, (lane >> 3) & 1);
    }

    if (t == 0) {
        #pragma unroll
        for (int s = 0; s < 3; s++) MBARRIER_INIT(MB + s * 8, 1);
    }
    __syncthreads();

    auto issue_pair = [&](int p) {
        const int s = p % 3;
        const uint32_t slot = sb + s * SLOT_BYTES;
        MBARRIER_EXPECT_TX(MB + s * 8, 32768u);
        BULK_G2S(slot,         Abase + (size_t)(2 * p) * 8192, 16384u, MB + s * 8);
        BULK_G2S(slot + 16384, Wbase + (size_t)(2 * p) * 8192, 16384u, MB + s * 8);
    };

    float acc[2][8][4];
    #pragma unroll
    for (int a = 0; a < 2; a++)
        #pragma unroll
        for (int b = 0; b < 8; b++)
            #pragma unroll
            for (int e = 0; e < 4; e++) acc[a][b][e] = 0.0f;

    uint32_t afr[2][2][4], wfr[2][4][4];
    auto load_frags = [&](int buf, uint32_t aa, uint32_t wa, int ks) {
        const uint32_t kx = ks ? 32u : 0u;
        #pragma unroll
        for (int tm = 0; tm < 2; tm++)
            LDSM_X4(afr[buf][tm], aa + (aoff[tm] ^ kx));
        #pragma unroll
        for (int p = 0; p < 4; p++)
            LDSM_X4(wfr[buf][p], wa + (woff[p] ^ kx));
    };
    auto mma_frags = [&](int buf) {
        #pragma unroll
        for (int tm = 0; tm < 2; tm++)
            #pragma unroll
            for (int tn = 0; tn < 8; tn++)
                MMA16816(acc[tm][tn], afr[buf][tm],
                         (&wfr[buf][tn >> 1][(tn & 1) * 2]));
    };
    auto compute_pair = [&](uint32_t slot) {
        const uint32_t a0 = slot, a1 = slot + 8192;
        const uint32_t w0 = slot + 16384, w1 = slot + 24576;
        load_frags(0, a0, w0, 0);
        load_frags(1, a0, w0, 1);  mma_frags(0);
        load_frags(0, a1, w1, 0);  mma_frags(1);
        load_frags(1, a1, w1, 1);  mma_frags(0);
        mma_frags(1);
    };

    if (t == 0) { issue_pair(0); issue_pair(1); }

    // main loop: sync (certify p-1 consumed) -> issue p+2 -> wait p -> compute
    for (int p = 0; p < 32; p++) {
        __syncthreads();
        if (p <= 29 && t == 0) issue_pair(p + 2);
        MBARRIER_WAIT_PARITY(MB + (p % 3) * 8, (p / 3) & 1);
        compute_pair(sb + (p % 3) * SLOT_BYTES);
    }

    // ===================== epilogue =========================================
    __syncthreads();   // all mainloop smem reads complete

    {
        const float* srcs[3] = {c_in, n_in, m_in};
        #pragma unroll
        for (int i = 0; i < 12; i++) {
            const int c = i * 256 + t;
            const int p = c >> 10, w = c & 1023;
            const int row = w >> 3, col16 = w & 7;
            const char* src = (const char*)srcs[p]
                + ((size_t)(mt * 128 + row) * HDIM + nt * 32) * 4 + col16 * 16;
            CP_ASYNC16(sb + PRE_OFF + p * 16384 + w * 16, src);
        }
        CP_COMMIT();
    }

    const int jc4 = t & 7;
    const int rp  = t >> 3;
    const int jj4 = jc4 * 4;
    float4 b4[4];
    #pragma unroll
    for (int g = 0; g < 4; g++)
        b4[g] = *(const float4*)(bias + g * HDIM + nt * 32 + jj4);

    float* smf = (float*)smraw;
    float* pre = (float*)(smraw + PRE_OFF);
    const size_t BH = (size_t)BATCH * HDIM;

    #pragma unroll
    for (int H = 0; H < 2; H++) {
        if (wm >> 1 == H) {
            #pragma unroll
            for (int tm = 0; tm < 2; tm++)
                #pragma unroll
                for (int tn = 0; tn < 8; tn++) {
                    const int row = (wm & 1) * 32 + tm * 16 + (lane >> 2);
                    const int col = wn * 64 + tn * 8 + (lane & 3) * 2;
                    smf[row * 132 + col]           = acc[tm][tn][0];
                    smf[row * 132 + col + 1]       = acc[tm][tn][1];
                    smf[(row + 8) * 132 + col]     = acc[tm][tn][2];
                    smf[(row + 8) * 132 + col + 1] = acc[tm][tn][3];
                }
        }
        if (H == 0) CP_WAIT0();
        __syncthreads();

        #pragma unroll
        for (int r2 = 0; r2 < 2; r2++) {
            const int rloc = rp * 2 + r2;
            const int grow = mt * 128 + H * 64 + rloc;
            const int prow = H * 64 + rloc;
            float4 c4 = *(float4*)(pre + 0 * 4096 + prow * 32 + jj4);
            float4 n4 = *(float4*)(pre + 1 * 4096 + prow * 32 + jj4);
            float4 m4 = *(float4*)(pre + 2 * 4096 + prow * 32 + jj4);
            float4 ho, co, no, mo4;
            const float* gr = smf + rloc * 132;
            #pragma unroll
            for (int e = 0; e < 4; e++) {
                const float iv = gr[0 * 32 + jj4 + e] + ((const float*)&b4[0])[e];
                const float fv = gr[1 * 32 + jj4 + e] + ((const float*)&b4[1])[e];
                const float zv = gr[2 * 32 + jj4 + e] + ((const float*)&b4[2])[e];
                const float ov = gr[3 * 32 + jj4 + e] + ((const float*)&b4[3])[e];
                const float cv = ((const float*)&c4)[e];
                const float nv = ((const float*)&n4)[e];
                const float mv = ((const float*)&m4)[e];
                const float mn = fmaxf(fv + mv, iv);
                const float fg = exp_approx(fv + mv - mn);
                const float ig = exp_approx(iv - mn);
                const float zg = tanh_approx(zv);
                const float og = 0.5f * tanh_approx(0.5f * ov) + 0.5f;
                const float cn = fg * cv + ig * zg;
                const float nn = fg * nv + ig;
                const float hn = og * cn * rcp_approx(fmaxf(fabsf(nn), 1.0f));
                ((float*)&ho)[e]  = hn;
                ((float*)&co)[e]  = cn;
                ((float*)&no)[e]  = nn;
                ((float*)&mo4)[e] = mn;
            }
            float* ob = out + (size_t)grow * HDIM + nt * 32 + jj4;
            *(float4*)(ob)           = ho;
            *(float4*)(ob + BH)      = co;
            *(float4*)(ob + 2 * BH)  = no;
            *(float4*)(ob + 3 * BH)  = mo4;
        }
        if (H == 0) __syncthreads();
    }
}

// ================================ launch ====================================
extern "C" void kernel_launch(void* const* d_in, const int* in_sizes, int n_in,
                              void* d_out, int out_size) {
    const float* x    = (const float*)d_in[0];
    const float* h    = (const float*)d_in[1];
    const float* c    = (const float*)d_in[2];
    const float* n    = (const float*)d_in[3];
    const float* m    = (const float*)d_in[4];
    const float* Wx   = (const float*)d_in[5];
    const float* Wh   = (const float*)d_in[6];
    const float* bias = (const float*)d_in[7];
    float* out = (float*)d_out;

    pack_kernel<<<10240, 128>>>(x, h, Wx, Wh);

    cudaFuncSetAttribute(slstm_main, cudaFuncAttributeMaxDynamicSharedMemorySize,
                         SMEM_TOTAL);
    dim3 grid(32, 128);   // (nt, mt)
    slstm_main<<<grid, 256, SMEM_TOTAL>>>(c, n, m, bias, out);
}

// round 16
// speedup vs baseline: 1.1422x; 1.0837x over previous
#include <cuda_runtime.h>
#include <cuda_fp16.h>
#include <cstdint>
#include <math.h>

// ============================================================================
// sLSTM cell: gates = [x|h] @ [Wx|Wh]^T + b, exp-gate epilogue.
// R16 = R15 with the mainloop CTA barrier REMOVED: per-slot "empty" mbarriers
//      (count=8, one arrive per warp after consuming a slot). Only thread 0
//      waits on empty before re-issuing; compute warps wait only on data.
//      Warps drift -> cross-warp LDSM/MMA overlap, no per-pair convoy.
// ============================================================================

#define BATCH 16384
#define HDIM  1024
#define NKT   64
#define APLANE 8192
#define SLOT_BYTES 32768                 // A(kt0)|A(kt1)|W(kt0)|W(kt1)
#define HDR_OFF (3 * SLOT_BYTES)         // 98304: 6 mbarriers live here
#define SMEM_TOTAL (HDR_OFF + 128)       // 98432 -> 2 CTAs/SM

#define XCHG_BYTES (64 * 132 * 4)        // 33792: half-tile fp32 exchange
#define PRE_OFF    XCHG_BYTES            // c/n/m prefetch: 3 x 16KB

__device__ __align__(16) __half g_Apack[(size_t)8192 * 4096]; // 67 MB
__device__ __align__(16) __half g_Wpack[(size_t)2048 * 4096]; // 17 MB

__device__ __forceinline__ uint32_t smem_u32(const void* p) {
    uint32_t a;
    asm("{ .reg .u64 t; cvta.to.shared.u64 t, %1; cvt.u32.u64 %0, t; }" : "=r"(a) : "l"(p));
    return a;
}
__device__ __forceinline__ float tanh_approx(float x) {
    float y;
    asm("tanh.approx.f32 %0, %1;" : "=f"(y) : "f"(x));
    return y;
}
__device__ __forceinline__ float rcp_approx(float x) {
    float y;
    asm("rcp.approx.f32 %0, %1;" : "=f"(y) : "f"(x));
    return y;
}
__device__ __forceinline__ float exp_approx(float x) {
    float y;
    asm("ex2.approx.f32 %0, %1;" : "=f"(y) : "f"(x * 1.442695041f));
    return y;
}

#define LDSM_X4(r, addr)                                                        \
    asm volatile("ldmatrix.sync.aligned.m8n8.x4.shared.b16 {%0,%1,%2,%3}, [%4];" \
                 : "=r"((r)[0]), "=r"((r)[1]), "=r"((r)[2]), "=r"((r)[3])       \
                 : "r"(addr))

#define MMA16816(d, a, b)                                                       \
    asm volatile("mma.sync.aligned.m16n8k16.row.col.f32.f16.f16.f32 "           \
                 "{%0,%1,%2,%3}, {%4,%5,%6,%7}, {%8,%9}, {%0,%1,%2,%3};"        \
                 : "+f"((d)[0]), "+f"((d)[1]), "+f"((d)[2]), "+f"((d)[3])       \
                 : "r"((a)[0]), "r"((a)[1]), "r"((a)[2]), "r"((a)[3]),          \
                   "r"((b)[0]), "r"((b)[1]))

#define CP_ASYNC16(dst, src) \
    asm volatile("cp.async.cg.shared.global [%0], [%1], 16;" :: "r"(dst), "l"(src))
#define CP_COMMIT() asm volatile("cp.async.commit_group;" ::: "memory")
#define CP_WAIT0()  asm volatile("cp.async.wait_group 0;" ::: "memory")

#define MBARRIER_INIT(addr, cnt) \
    asm volatile("mbarrier.init.shared.b64 [%0], %1;" :: "r"(addr), "r"(cnt) : "memory")
#define MBARRIER_EXPECT_TX(addr, bytes) \
    asm volatile("mbarrier.arrive.expect_tx.shared.b64 _, [%0], %1;" :: "r"(addr), "r"(bytes) : "memory")
#define MBARRIER_ARRIVE(addr) \
    asm volatile("mbarrier.arrive.shared.b64 _, [%0];" :: "r"(addr) : "memory")
#define BULK_G2S(dst, src, bytes, mbar)                                                      \
    asm volatile("cp.async.bulk.shared::cta.global.mbarrier::complete_tx::bytes "            \
                 "[%0], [%1], %2, [%3];"                                                     \
                 :: "r"(dst), "l"(src), "r"(bytes), "r"(mbar) : "memory")

#define MBARRIER_WAIT_PARITY(mbar, parity) do {                                   \
    uint32_t _m = (mbar); uint32_t _p = (parity); uint32_t _d;                    \
    asm volatile("{\n\t.reg .pred p;\n\t"                                         \
        "mbarrier.try_wait.parity.acquire.cta.shared::cta.b64 p, [%1], %2;\n\t"   \
        "selp.b32 %0, 1, 0, p;\n\t}"                                              \
        : "=r"(_d) : "r"(_m), "r"(_p) : "memory");                                \
    if (!_d) {                                                                    \
        asm volatile("{\n\t.reg .pred P1;\n\t"                                    \
            "WL_%=:\n\t"                                                          \
            "mbarrier.try_wait.parity.acquire.cta.shared::cta.b64 P1, [%0], %1, 0x989680;\n\t" \
            "@P1 bra.uni WD_%=;\n\t"                                              \
            "bra.uni WL_%=;\n\t"                                                  \
            "WD_%=:\n\t}"                                                         \
            :: "r"(_m), "r"(_p) : "memory");                                      \
    }                                                                             \
} while (0)

__device__ __forceinline__ uint32_t swz(int row, int ch) {
    return (uint32_t)(row * 64 + ((ch ^ ((row >> 1) & 3)) << 4));
}

// ============================== pack kernel =================================
__global__ __launch_bounds__(128) void pack_kernel(
    const float* __restrict__ x, const float* __restrict__ h,
    const float* __restrict__ Wx, const float* __restrict__ Wh)
{
    const int bt = blockIdx.x, t = threadIdx.x;
    const bool isA = bt < 8192;
    const int tile = isA ? bt : bt - 8192;
    const int kt = tile & 63;
    const int rt = tile >> 6;
    const float* src = (kt < 32) ? (isA ? x : Wx) : (isA ? h : Wh);
    const int kbase = (kt & 31) * 32;
    __half* dst = (isA ? g_Apack : g_Wpack) + (size_t)tile * 4096;

    #pragma unroll
    for (int i = 0; i < 8; i++) {
        const int cc = i * 128 + t;
        const int r = cc >> 3, k4 = cc & 7;
        const int grow = isA ? (rt * 128 + r)
                             : ((r >> 5) * HDIM + rt * 32 + (r & 31));
        float4 v = *(const float4*)(src + (size_t)grow * 1024 + kbase + k4 * 4);
        __half2 p0 = __floats2half2_rn(v.x, v.y);
        __half2 p1 = __floats2half2_rn(v.z, v.w);
        const int eoff = r * 32 + (((k4 >> 1) ^ ((r >> 1) & 3)) << 3) + (k4 & 1) * 4;
        *(uint2*)(dst + eoff) = make_uint2(*(uint32_t*)&p0, *(uint32_t*)&p1);
    }
}

// =============================== main kernel ================================
__global__ __launch_bounds__(256, 2) void slstm_main(
    const float* __restrict__ c_in, const float* __restrict__ n_in,
    const float* __restrict__ m_in, const float* __restrict__ bias,
    float* __restrict__ out)
{
    extern __shared__ char smraw[];
    const uint32_t sb = smem_u32(smraw);
    const int t = threadIdx.x, lane = t & 31, wid = t >> 5;
    const int nt = blockIdx.x, mt = blockIdx.y;
    const int wm = wid >> 1, wn = wid & 1;
    const uint32_t MBF = sb + HDR_OFF;        // full[0..2] @ +0,8,16
    const uint32_t MBE = sb + HDR_OFF + 24;   // empty[0..2] @ +24,32,40

    const char* Abase = (const char*)g_Apack + (size_t)(mt * 64) * 8192;
    const char* Wbase = (const char*)g_Wpack + (size_t)(nt * 64) * 8192;

    uint32_t aoff[2], woff[4];
    #pragma unroll
    for (int tm = 0; tm < 2; tm++) {
        const int r = wm * 32 + tm * 16 + (lane & 15);
        aoff[tm] = swz(r, lane >> 4);
    }
    #pragma unroll
    for (int p = 0; p < 4; p++) {
        const int r = wn * 64 + p * 16 + ((lane >> 4) << 3) + (lane & 7);
        woff[p] = swz(r, (lane >> 3) & 1);
    }

    if (t == 0) {
        #pragma unroll
        for (int s = 0; s < 3; s++) {
            MBARRIER_INIT(MBF + s * 8, 1);    // full: tx-based
            MBARRIER_INIT(MBE + s * 8, 8);    // empty: one arrive per warp
        }
    }
    __syncthreads();

    auto issue_pair = [&](int p) {
        const int s = p % 3;
        const uint32_t slot = sb + s * SLOT_BYTES;
        MBARRIER_EXPECT_TX(MBF + s * 8, 32768u);
        BULK_G2S(slot,         Abase + (size_t)(2 * p) * 8192, 16384u, MBF + s * 8);
        BULK_G2S(slot + 16384, Wbase + (size_t)(2 * p) * 8192, 16384u, MBF + s * 8);
    };

    float acc[2][8][4];
    #pragma unroll
    for (int a = 0; a < 2; a++)
        #pragma unroll
        for (int b = 0; b < 8; b++)
            #pragma unroll
            for (int e = 0; e < 4; e++) acc[a][b][e] = 0.0f;

    uint32_t afr[2][2][4], wfr[2][4][4];
    auto load_frags = [&](int buf, uint32_t aa, uint32_t wa, int ks) {
        const uint32_t kx = ks ? 32u : 0u;
        #pragma unroll
        for (int tm = 0; tm < 2; tm++)
            LDSM_X4(afr[buf][tm], aa + (aoff[tm] ^ kx));
        #pragma unroll
        for (int p = 0; p < 4; p++)
            LDSM_X4(wfr[buf][p], wa + (woff[p] ^ kx));
    };
    auto mma_frags = [&](int buf) {
        #pragma unroll
        for (int tm = 0; tm < 2; tm++)
            #pragma unroll
            for (int tn = 0; tn < 8; tn++)
                MMA16816(acc[tm][tn], afr[buf][tm],
                         (&wfr[buf][tn >> 1][(tn & 1) * 2]));
    };
    auto compute_pair = [&](uint32_t slot) {
        const uint32_t a0 = slot, a1 = slot + 8192;
        const uint32_t w0 = slot + 16384, w1 = slot + 24576;
        load_frags(0, a0, w0, 0);
        load_frags(1, a0, w0, 1);  mma_frags(0);
        load_frags(0, a1, w1, 0);  mma_frags(1);
        load_frags(1, a1, w1, 1);  mma_frags(0);
        mma_frags(1);
    };

    if (t == 0) { issue_pair(0); issue_pair(1); }   // slots 0,1, first use

    // mainloop: NO CTA barrier. Producer (t0) gates slot reuse on the empty
    // barrier (8 warp-arrivals for the slot's previous pair); consumer warps
    // wait only on data (full). Pair p -> slot p%3, use index k = p/3.
    for (int p = 0; p < 32; p++) {
        if (t == 0 && p <= 29) {
            const int q = p + 2, s = q % 3, k = q / 3;
            if (k >= 1) MBARRIER_WAIT_PARITY(MBE + s * 8, (k - 1) & 1);
            issue_pair(q);
        }
        MBARRIER_WAIT_PARITY(MBF + (p % 3) * 8, (p / 3) & 1);
        compute_pair(sb + (p % 3) * SLOT_BYTES);
        if (lane == 0) MBARRIER_ARRIVE(MBE + (p % 3) * 8);
    }

    // ===================== epilogue (R12/R15 scheme) ========================
    __syncthreads();   // all warps done with mainloop smem

    {
        const float* srcs[3] = {c_in, n_in, m_in};
        #pragma unroll
        for (int i = 0; i < 12; i++) {
            const int c = i * 256 + t;
            const int p = c >> 10, w = c & 1023;
            const int row = w >> 3, col16 = w & 7;
            const char* src = (const char*)srcs[p]
                + ((size_t)(mt * 128 + row) * HDIM + nt * 32) * 4 + col16 * 16;
            CP_ASYNC16(sb + PRE_OFF + p * 16384 + w * 16, src);
        }
        CP_COMMIT();
    }

    const int jc4 = t & 7;
    const int rp  = t >> 3;
    const int jj4 = jc4 * 4;
    float4 b4[4];
    #pragma unroll
    for (int g = 0; g < 4; g++)
        b4[g] = *(const float4*)(bias + g * HDIM + nt * 32 + jj4);

    float* smf = (float*)smraw;
    float* pre = (float*)(smraw + PRE_OFF);
    const size_t BH = (size_t)BATCH * HDIM;

    #pragma unroll
    for (int H = 0; H < 2; H++) {
        if (wm >> 1 == H) {
            #pragma unroll
            for (int tm = 0; tm < 2; tm++)
                #pragma unroll
                for (int tn = 0; tn < 8; tn++) {
                    const int row = (wm & 1) * 32 + tm * 16 + (lane >> 2);
                    const int col = wn * 64 + tn * 8 + (lane & 3) * 2;
                    smf[row * 132 + col]           = acc[tm][tn][0];
                    smf[row * 132 + col + 1]       = acc[tm][tn][1];
                    smf[(row + 8) * 132 + col]     = acc[tm][tn][2];
                    smf[(row + 8) * 132 + col + 1] = acc[tm][tn][3];
                }
        }
        if (H == 0) CP_WAIT0();
        __syncthreads();

        #pragma unroll
        for (int r2 = 0; r2 < 2; r2++) {
            const int rloc = rp * 2 + r2;
            const int grow = mt * 128 + H * 64 + rloc;
            const int prow = H * 64 + rloc;
            float4 c4 = *(float4*)(pre + 0 * 4096 + prow * 32 + jj4);
            float4 n4 = *(float4*)(pre + 1 * 4096 + prow * 32 + jj4);
            float4 m4 = *(float4*)(pre + 2 * 4096 + prow * 32 + jj4);
            float4 ho, co, no, mo4;
            const float* gr = smf + rloc * 132;
            #pragma unroll
            for (int e = 0; e < 4; e++) {
                const float iv = gr[0 * 32 + jj4 + e] + ((const float*)&b4[0])[e];
                const float fv = gr[1 * 32 + jj4 + e] + ((const float*)&b4[1])[e];
                const float zv = gr[2 * 32 + jj4 + e] + ((const float*)&b4[2])[e];
                const float ov = gr[3 * 32 + jj4 + e] + ((const float*)&b4[3])[e];
                const float cv = ((const float*)&c4)[e];
                const float nv = ((const float*)&n4)[e];
                const float mv = ((const float*)&m4)[e];
                const float mn = fmaxf(fv + mv, iv);
                const float fg = exp_approx(fv + mv - mn);
                const float ig = exp_approx(iv - mn);
                const float zg = tanh_approx(zv);
                const float og = 0.5f * tanh_approx(0.5f * ov) + 0.5f;
                const float cn = fg * cv + ig * zg;
                const float nn = fg * nv + ig;
                const float hn = og * cn * rcp_approx(fmaxf(fabsf(nn), 1.0f));
                ((float*)&ho)[e]  = hn;
                ((float*)&co)[e]  = cn;
                ((float*)&no)[e]  = nn;
                ((float*)&mo4)[e] = mn;
            }
            float* ob = out + (size_t)grow * HDIM + nt * 32 + jj4;
            *(float4*)(ob)           = ho;
            *(float4*)(ob + BH)      = co;
            *(float4*)(ob + 2 * BH)  = no;
            *(float4*)(ob + 3 * BH)  = mo4;
        }
        if (H == 0) __syncthreads();
    }
}

// ================================ launch ====================================
extern "C" void kernel_launch(void* const* d_in, const int* in_sizes, int n_in,
                              void* d_out, int out_size) {
    const float* x    = (const float*)d_in[0];
    const float* h    = (const float*)d_in[1];
    const float* c    = (const float*)d_in[2];
    const float* n    = (const float*)d_in[3];
    const float* m    = (const float*)d_in[4];
    const float* Wx   = (const float*)d_in[5];
    const float* Wh   = (const float*)d_in[6];
    const float* bias = (const float*)d_in[7];
    float* out = (float*)d_out;

    pack_kernel<<<10240, 128>>>(x, h, Wx, Wh);

    cudaFuncSetAttribute(slstm_main, cudaFuncAttributeMaxDynamicSharedMemorySize,
                         SMEM_TOTAL);
    dim3 grid(32, 128);   // (nt, mt)
    slstm_main<<<grid, 256, SMEM_TOTAL>>>(c, n, m, bias, out);
}